// round 17
// baseline (speedup 1.0000x reference)
#include <cuda_runtime.h>
#include <cuda_fp16.h>
#include <math.h>
#include <stdint.h>

// ---------------------------------------------------------------------------
// Problem constants
// ---------------------------------------------------------------------------
#define S_LEN   2048
#define D_MODEL 2048
#define NHEADS  16
#define HDIM    128
#define BATCH   2
#define NTOK    (BATCH * S_LEN)   // 4096
#define QKV_N   (3 * D_MODEL)     // 6144
#define BH      (BATCH * NHEADS)  // 32

// ---------------------------------------------------------------------------
// Scratch (device globals -- no allocation allowed in kernel_launch)
// ---------------------------------------------------------------------------
__device__ uint32_t g_xh[NTOK * D_MODEL / 2];        // x fp16 pairs [M][K/2]
__device__ uint32_t g_wqkvh[QKV_N * (D_MODEL / 2)];  // w_qkv T-packed [N][K/2]
__device__ uint32_t g_woh[D_MODEL * (D_MODEL / 2)];  // w_o  T-packed [N][K/2]
__device__ uint32_t g_qh[BH * S_LEN * HDIM / 2];     // Q fp16 [row][64] (roped)
__device__ uint32_t g_kh[BH * S_LEN * HDIM / 2];     // K fp16 [row][64] (roped)
__device__ uint32_t g_vn[BH * S_LEN * HDIM / 2];     // V fp16 natural [row][64]
__device__ uint32_t g_attnh[NTOK * D_MODEL / 2];     // attn out fp16 pairs
__device__ float2   g_ctab[S_LEN * 64];              // (cos,sin) per (s, j)

// ---------------------------------------------------------------------------
// helpers
// ---------------------------------------------------------------------------
__device__ __forceinline__ void mma_f16(float c[4],
                                        uint32_t a0, uint32_t a1,
                                        uint32_t a2, uint32_t a3,
                                        uint32_t b0, uint32_t b1) {
    asm volatile(
        "mma.sync.aligned.m16n8k16.row.col.f32.f16.f16.f32 "
        "{%0,%1,%2,%3}, {%4,%5,%6,%7}, {%8,%9}, {%0,%1,%2,%3};"
        : "+f"(c[0]), "+f"(c[1]), "+f"(c[2]), "+f"(c[3])
        : "r"(a0), "r"(a1), "r"(a2), "r"(a3), "r"(b0), "r"(b1));
}
__device__ __forceinline__ void cp16(uint32_t dst, const void* src) {
    asm volatile("cp.async.cg.shared.global [%0], [%1], 16;"
                 :: "r"(dst), "l"(src));
}
__device__ __forceinline__ uint32_t packh2(float a, float b) {
    __half2 h = __floats2half2_rn(a, b);
    return *(uint32_t*)&h;
}
__device__ __forceinline__ void ldsm4(uint32_t r[4], uint32_t addr) {
    asm volatile("ldmatrix.sync.aligned.m8n8.x4.shared.b16 {%0,%1,%2,%3}, [%4];"
                 : "=r"(r[0]), "=r"(r[1]), "=r"(r[2]), "=r"(r[3]) : "r"(addr));
}
__device__ __forceinline__ void ldsm4t(uint32_t r[4], uint32_t addr) {
    asm volatile("ldmatrix.sync.aligned.m8n8.x4.trans.shared.b16 {%0,%1,%2,%3}, [%4];"
                 : "=r"(r[0]), "=r"(r[1]), "=r"(r[2]), "=r"(r[3]) : "r"(addr));
}

// ---------------------------------------------------------------------------
// Prep kernels
// ---------------------------------------------------------------------------
__global__ void f32_to_h16(const float4* __restrict__ in,
                           uint32_t* __restrict__ out, int n4)
{
    int i = blockIdx.x * blockDim.x + threadIdx.x;
    if (i < n4) {
        float4 v = in[i];
        out[2 * i + 0] = packh2(v.x, v.y);
        out[2 * i + 1] = packh2(v.z, v.w);
    }
}

// Transposing weight pack: in [K][N] f32 -> out [N][K/2] fp16-pair words.
__global__ void pack_w16t(const float* __restrict__ in,
                          uint32_t* __restrict__ out, int N, int K)
{
    __shared__ float sm[64][33];
    const int n0 = blockIdx.x * 32;
    const int k0 = blockIdx.y * 64;
    const int tid = threadIdx.x;
#pragma unroll
    for (int i = 0; i < 8; i++) {
        int r = i * 8 + (tid >> 5);
        int n = tid & 31;
        sm[r][n] = in[(size_t)(k0 + r) * N + n0 + n];
    }
    __syncthreads();
    const int Kw = K >> 1;
#pragma unroll
    for (int i = 0; i < 4; i++) {
        int idx = i * 256 + tid;
        int n = idx >> 5, kkl = idx & 31;
        out[(size_t)(n0 + n) * Kw + (k0 >> 1) + kkl] =
            packh2(sm[2 * kkl][n], sm[2 * kkl + 1][n]);
    }
}

// cos/sin table (positions int64/int32 auto-detect)
__global__ void build_ctab(float2* __restrict__ ctab,
                           const int* __restrict__ pos32)
{
    const int s = blockIdx.x;
    const int j = threadIdx.x;
    const bool is64 = (pos32[1] == 0);
    const int  p    = is64 ? pos32[2 * s] : pos32[s];
    float inv = powf(10000.0f, -(float)(2 * j) * (1.0f / 128.0f));
    float sn, cs;
    sincosf((float)p * inv, &sn, &cs);
    ctab[s * 64 + j] = make_float2(cs, sn);
}

// ---------------------------------------------------------------------------
// fp16 HMMA GEMM (m16n8k16), cp.async 3-stage, BK=64, ldmatrix fragments.
// A: [M][K/2] words.  B: T-packed [N][K/2] words (same tile shape as A).
// 128 threads, 4 warps (2x2) of 64x64, manual fragment double-buffer.
// MODE 0: plain f32 store.  MODE 1: fused RoPE -> fp16 Q/K/V.
// ---------------------------------------------------------------------------
#define TBM 128
#define TBN 128
#define TBKW 32          // 64 k-elements = 32 pair-words
#define TSTR 36          // tile row stride (words)
#define STG  3
#define AS_W (TBM * TSTR)            // 4608
#define BS_W (TBN * TSTR)            // 4608
#define STAGE_W (AS_W + BS_W)        // 9216
#define GEMM_SMEM (STG * STAGE_W * 4)  // 110592 B

template <int MODE>
__global__ __launch_bounds__(128, 2)
void h16_gemm(const uint32_t* __restrict__ A, const uint32_t* __restrict__ B,
              float* __restrict__ C,
              uint32_t* __restrict__ Qh, uint32_t* __restrict__ Kh,
              uint32_t* __restrict__ Vn,
              const float2* __restrict__ ctab,
              int N, int K)
{
    extern __shared__ uint32_t smw[];
    const uint32_t sb = (uint32_t)__cvta_generic_to_shared(smw);

    const int tid  = threadIdx.x;
    const int lane = tid & 31;
    const int wid  = tid >> 5;
    const int wm   = wid >> 1;
    const int wn   = wid & 1;
    const int g    = lane >> 2;
    const int q    = lane & 3;
    const int l7   = lane & 7;
    const int lb8  = (lane >> 3) & 1;
    const int lb16 = (lane >> 4) & 1;

    const int brow = blockIdx.y;
    const int bcol = blockIdx.x;
    const int Kw   = K >> 1;
    const uint32_t* Ab = A + (size_t)brow * TBM * Kw;
    const uint32_t* Bb = B + (size_t)bcol * TBN * Kw;

    int aoff[4], boff[4];
#pragma unroll
    for (int tm = 0; tm < 4; tm++)
        aoff[tm] = (wm * 64 + tm * 16 + l7 + 8 * lb8) * TSTR + 4 * lb16;
#pragma unroll
    for (int p = 0; p < 4; p++)
        boff[p] = (wn * 64 + p * 16 + l7 + 8 * lb16) * TSTR + 4 * lb8;

    const int T = K / 64;

#pragma unroll
    for (int p = 0; p < STG - 1; p++) {
        const uint32_t sa  = sb + (uint32_t)(p * STAGE_W) * 4u;
        const uint32_t sbb = sa + (uint32_t)AS_W * 4u;
        const int ktw = p * TBKW;
#pragma unroll
        for (int i = 0; i < 8; i++) {
            const int c   = tid + i * 128;
            const int row = c >> 3, cw = (c & 7) << 2;
            cp16(sa  + (uint32_t)(row * TSTR + cw) * 4u,
                 Ab + (size_t)row * Kw + ktw + cw);
            cp16(sbb + (uint32_t)(row * TSTR + cw) * 4u,
                 Bb + (size_t)row * Kw + ktw + cw);
        }
        asm volatile("cp.async.commit_group;");
    }

    float acc[4][8][4];
#pragma unroll
    for (int i = 0; i < 4; i++)
#pragma unroll
        for (int j = 0; j < 8; j++)
#pragma unroll
            for (int r = 0; r < 4; r++) acc[i][j][r] = 0.0f;

    uint32_t af[2][4][4], bf[2][8][2];

    int stage = 0;
    for (int t = 0; t < T; t++) {
        asm volatile("cp.async.wait_group %0;" :: "n"(STG - 2));
        __syncthreads();

        {
            const int tn = t + STG - 1;
            if (tn < T) {
                int st = stage + (STG - 1);
                if (st >= STG) st -= STG;
                const uint32_t sa  = sb + (uint32_t)(st * STAGE_W) * 4u;
                const uint32_t sbb = sa + (uint32_t)AS_W * 4u;
                const int ktw = tn * TBKW;
#pragma unroll
                for (int i = 0; i < 8; i++) {
                    const int c   = tid + i * 128;
                    const int row = c >> 3, cw = (c & 7) << 2;
                    cp16(sa  + (uint32_t)(row * TSTR + cw) * 4u,
                         Ab + (size_t)row * Kw + ktw + cw);
                    cp16(sbb + (uint32_t)(row * TSTR + cw) * 4u,
                         Bb + (size_t)row * Kw + ktw + cw);
                }
            }
            asm volatile("cp.async.commit_group;");
        }

        const uint32_t sa  = sb + (uint32_t)(stage * STAGE_W) * 4u;
        const uint32_t sbb = sa + (uint32_t)AS_W * 4u;

        auto ldfrag = [&](uint32_t afr[4][4], uint32_t bfr[8][2], int kw) {
#pragma unroll
            for (int tm = 0; tm < 4; tm++)
                ldsm4(afr[tm], sa + (uint32_t)(aoff[tm] + kw) * 4u);
#pragma unroll
            for (int p = 0; p < 4; p++) {
                uint32_t tmp[4];
                ldsm4(tmp, sbb + (uint32_t)(boff[p] + kw) * 4u);
                bfr[2 * p][0] = tmp[0]; bfr[2 * p][1] = tmp[1];
                bfr[2 * p + 1][0] = tmp[2]; bfr[2 * p + 1][1] = tmp[3];
            }
        };

        ldfrag(af[0], bf[0], 0);
#pragma unroll
        for (int s = 0; s < 4; s++) {
            const int cur = s & 1;
            const int nxt = cur ^ 1;
            if (s + 1 < 4) ldfrag(af[nxt], bf[nxt], (s + 1) * 8);
#pragma unroll
            for (int tm = 0; tm < 4; tm++)
#pragma unroll
                for (int tn2 = 0; tn2 < 8; tn2++)
                    mma_f16(acc[tm][tn2],
                            af[cur][tm][0], af[cur][tm][1],
                            af[cur][tm][2], af[cur][tm][3],
                            bf[cur][tn2][0], bf[cur][tn2][1]);
        }
        if (++stage == STG) stage = 0;
    }

    // ---------------- epilogue ----------------
    if (MODE == 0) {
#pragma unroll
        for (int tm = 0; tm < 4; tm++) {
            const int row = brow * TBM + wm * 64 + tm * 16 + g;
#pragma unroll
            for (int tn2 = 0; tn2 < 8; tn2++) {
                const int col = bcol * TBN + wn * 64 + tn2 * 8 + 2 * q;
                *(float2*)&C[(size_t)row * N + col] =
                    make_float2(acc[tm][tn2][0], acc[tm][tn2][1]);
                *(float2*)&C[(size_t)(row + 8) * N + col] =
                    make_float2(acc[tm][tn2][2], acc[tm][tn2][3]);
            }
        }
    } else {
        const int col0  = bcol * TBN;
        const int which = col0 >> 11;
        const int h     = (col0 & 2047) >> 7;
        uint32_t* dst = (which == 0) ? Qh : ((which == 1) ? Kh : Vn);
#pragma unroll
        for (int tm = 0; tm < 4; tm++) {
            const int rowtok = brow * TBM + wm * 64 + tm * 16 + g;
            const int bb  = rowtok >> 11;
            const int ss  = rowtok & 2047;
            const int rt8 = rowtok + 8;
            const int bb8 = rt8 >> 11;
            const int ss8 = rt8 & 2047;
            uint32_t* b0 = dst + ((size_t)(bb  * NHEADS + h) * S_LEN + ss)  * 64;
            uint32_t* b8 = dst + ((size_t)(bb8 * NHEADS + h) * S_LEN + ss8) * 64;
#pragma unroll
            for (int tn2 = 0; tn2 < 8; tn2++) {
                const int jl = wn * 32 + tn2 * 4 + q;
                if (which < 2) {
                    const float2 c0 = ctab[ss  * 64 + jl];
                    const float2 c8 = ctab[ss8 * 64 + jl];
                    float x1 = acc[tm][tn2][0], x2 = acc[tm][tn2][1];
                    b0[jl] = packh2(x1 * c0.x - x2 * c0.y, x1 * c0.y + x2 * c0.x);
                    x1 = acc[tm][tn2][2]; x2 = acc[tm][tn2][3];
                    b8[jl] = packh2(x1 * c8.x - x2 * c8.y, x1 * c8.y + x2 * c8.x);
                } else {
                    b0[jl] = packh2(acc[tm][tn2][0], acc[tm][tn2][1]);
                    b8[jl] = packh2(acc[tm][tn2][2], acc[tm][tn2][3]);
                }
            }
        }
    }
}

// ---------------------------------------------------------------------------
// Flash attention, fp16 HMMA + ldmatrix, causal, online softmax.
// Q/K/V smem all [row][QSH]; V fragments via ldmatrix.trans from [s][d].
// NOW 2 CTAs/SM (smem 104448 x 2 fits the 228KB carveout): co-resident CTA
// fills the tensor pipe during this CTA's softmax/shuffle phases, and wave
// count drops 3.46 -> 1.73 (heavy-first qb ordering packs the tail).
// Block: 128 q-rows, 8 warps x 16 rows, 256 threads.  Output fp16 pairs.
// ---------------------------------------------------------------------------
#define FQ   128
#define FKT  64
#define QSH  68     // row stride (words)
#define SW_K0 (FQ * QSH)                  // 8704
#define SW_V0 (SW_K0 + 2 * FKT * QSH)     // 17408
#define FLASH_H_SMEM ((SW_V0 + 2 * FKT * QSH) * 4)   // 104448 B

__global__ __launch_bounds__(256, 2)
void flash_h16(const uint32_t* __restrict__ Qh, const uint32_t* __restrict__ Kh,
               const uint32_t* __restrict__ Vn, uint32_t* __restrict__ Oh)
{
    extern __shared__ uint32_t smw[];
    const int tid  = threadIdx.x;
    const int lane = tid & 31;
    const int w    = tid >> 5;
    const int g    = lane >> 2;
    const int q    = lane & 3;
    const int l7   = lane & 7;
    const int lb8  = (lane >> 3) & 1;
    const int lb16 = (lane >> 4) & 1;

    const int qb = (int)(gridDim.x - 1 - blockIdx.x);   // heavy blocks first
    const int h  = blockIdx.y;
    const int b  = blockIdx.z;
    const int bh = b * NHEADS + h;

    const uint32_t* Qg = Qh + ((size_t)bh * S_LEN + (size_t)qb * FQ) * 64;
    const uint32_t* Kg = Kh + (size_t)bh * S_LEN * 64;
    const uint32_t* Vg = Vn + (size_t)bh * S_LEN * 64;

    const uint32_t sb = (uint32_t)__cvta_generic_to_shared(smw);

    // ldmatrix base offsets
    const int qoff = (w * 16 + l7 + 8 * lb8) * QSH + 4 * lb16;
    int koff[4], voff[8];
#pragma unroll
    for (int p = 0; p < 4; p++)
        koff[p] = (p * 16 + l7 + 8 * lb16) * QSH + 4 * lb8;
    // V (.trans): matrices 0/1 = k-rows 0-7/8-15 at d0; 2/3 = same at d0+8
#pragma unroll
    for (int p = 0; p < 8; p++)
        voff[p] = (l7 + 8 * lb8) * QSH + p * 8 + 4 * lb16;

    // Q tile: 2048 chunks, 8/thread
#pragma unroll
    for (int i = 0; i < 8; i++) {
        int c   = i * 256 + tid;
        int row = c >> 4, cw = (c & 15) << 2;
        cp16(sb + (uint32_t)(row * QSH + cw) * 4u, Qg + (size_t)row * 64 + cw);
    }
    // K tile 0 + V tile 0: 1024 chunks each, 4+4/thread
#pragma unroll
    for (int i = 0; i < 4; i++) {
        int c = i * 256 + tid;
        int row = c >> 4, cw = (c & 15) << 2;
        cp16(sb + (uint32_t)(SW_K0 + row * QSH + cw) * 4u,
             Kg + (size_t)row * 64 + cw);
        cp16(sb + (uint32_t)(SW_V0 + row * QSH + cw) * 4u,
             Vg + (size_t)row * 64 + cw);
    }
    asm volatile("cp.async.commit_group;");

    float m0 = -1e30f, m1 = -1e30f, l0 = 0.0f, l1 = 0.0f;
    float acc[16][4];
#pragma unroll
    for (int nf = 0; nf < 16; nf++)
#pragma unroll
        for (int c = 0; c < 4; c++) acc[nf][c] = 0.0f;

    const float SC = 0.088388347648318447f;
    const int ntiles = 2 * qb + 2;
    const int r0 = qb * FQ + w * 16 + g;
    const int r1 = r0 + 8;

    for (int kt = 0; kt < ntiles; kt++) {
        asm volatile("cp.async.wait_group 0;");
        __syncthreads();

        if (kt + 1 < ntiles) {
            const int nb = (kt + 1) & 1;
            const uint32_t* Ks = Kg + (size_t)(kt + 1) * FKT * 64;
            const uint32_t* Vs = Vg + (size_t)(kt + 1) * FKT * 64;
#pragma unroll
            for (int i = 0; i < 4; i++) {
                int c = i * 256 + tid;
                int row = c >> 4, cw = (c & 15) << 2;
                cp16(sb + (uint32_t)(SW_K0 + nb * FKT * QSH + row * QSH + cw) * 4u,
                     Ks + (size_t)row * 64 + cw);
                cp16(sb + (uint32_t)(SW_V0 + nb * FKT * QSH + row * QSH + cw) * 4u,
                     Vs + (size_t)row * 64 + cw);
            }
            asm volatile("cp.async.commit_group;");
        }

        if (kt * FKT <= qb * FQ + w * 16 + 15) {
            const uint32_t sqb = sb;
            const uint32_t skb = sb + (uint32_t)(SW_K0 + (kt & 1) * FKT * QSH) * 4u;
            const uint32_t svb = sb + (uint32_t)(SW_V0 + (kt & 1) * FKT * QSH) * 4u;

            // ---- S = Q K^T ----
            float sc[8][4];
#pragma unroll
            for (int nf = 0; nf < 8; nf++)
#pragma unroll
                for (int c = 0; c < 4; c++) sc[nf][c] = 0.0f;

#pragma unroll
            for (int ds = 0; ds < 8; ds++) {
                const int kw = ds * 8;
                uint32_t a[4];
                ldsm4(a, sqb + (uint32_t)(qoff + kw) * 4u);
#pragma unroll
                for (int p = 0; p < 4; p++) {
                    uint32_t kb[4];
                    ldsm4(kb, skb + (uint32_t)(koff[p] + kw) * 4u);
                    mma_f16(sc[2 * p],     a[0], a[1], a[2], a[3], kb[0], kb[1]);
                    mma_f16(sc[2 * p + 1], a[0], a[1], a[2], a[3], kb[2], kb[3]);
                }
            }

            // ---- causal mask ----
            if (kt * FKT + FKT - 1 > r0) {
#pragma unroll
                for (int nf = 0; nf < 8; nf++) {
#pragma unroll
                    for (int cb = 0; cb < 2; cb++) {
                        int kcol = kt * FKT + nf * 8 + 2 * q + cb;
                        if (kcol > r0) sc[nf][cb]     = -1e30f;
                        if (kcol > r1) sc[nf][2 + cb] = -1e30f;
                    }
                }
            }

            // ---- online softmax (quad-local) ----
            float mx0 = -1e30f, mx1 = -1e30f;
#pragma unroll
            for (int nf = 0; nf < 8; nf++) {
                mx0 = fmaxf(mx0, fmaxf(sc[nf][0], sc[nf][1]));
                mx1 = fmaxf(mx1, fmaxf(sc[nf][2], sc[nf][3]));
            }
            mx0 = fmaxf(mx0, __shfl_xor_sync(0xffffffffu, mx0, 1));
            mx0 = fmaxf(mx0, __shfl_xor_sync(0xffffffffu, mx0, 2));
            mx1 = fmaxf(mx1, __shfl_xor_sync(0xffffffffu, mx1, 1));
            mx1 = fmaxf(mx1, __shfl_xor_sync(0xffffffffu, mx1, 2));

            float mn0 = fmaxf(m0, mx0), mn1 = fmaxf(m1, mx1);
            float al0 = __expf(SC * (m0 - mn0));
            float al1 = __expf(SC * (m1 - mn1));
            m0 = mn0; m1 = mn1;

            float rs0 = 0.0f, rs1 = 0.0f;
#pragma unroll
            for (int nf = 0; nf < 8; nf++) {
                float p0 = __half2float(__float2half_rn(__expf(SC * (sc[nf][0] - m0))));
                float p1 = __half2float(__float2half_rn(__expf(SC * (sc[nf][1] - m0))));
                float p2 = __half2float(__float2half_rn(__expf(SC * (sc[nf][2] - m1))));
                float p3 = __half2float(__float2half_rn(__expf(SC * (sc[nf][3] - m1))));
                sc[nf][0] = p0; sc[nf][1] = p1; sc[nf][2] = p2; sc[nf][3] = p3;
                rs0 += p0 + p1;
                rs1 += p2 + p3;
            }
            rs0 += __shfl_xor_sync(0xffffffffu, rs0, 1);
            rs0 += __shfl_xor_sync(0xffffffffu, rs0, 2);
            rs1 += __shfl_xor_sync(0xffffffffu, rs1, 1);
            rs1 += __shfl_xor_sync(0xffffffffu, rs1, 2);
            l0 = l0 * al0 + rs0;
            l1 = l1 * al1 + rs1;

#pragma unroll
            for (int nf = 0; nf < 16; nf++) {
                acc[nf][0] *= al0; acc[nf][1] *= al0;
                acc[nf][2] *= al1; acc[nf][3] *= al1;
            }

            // ---- O += P V : V B-frags via ldmatrix.trans from [s][d] ----
#pragma unroll
            for (int j = 0; j < 4; j++) {
                uint32_t pa0 = packh2(sc[2 * j][0],     sc[2 * j][1]);
                uint32_t pa1 = packh2(sc[2 * j][2],     sc[2 * j][3]);
                uint32_t pa2 = packh2(sc[2 * j + 1][0], sc[2 * j + 1][1]);
                uint32_t pa3 = packh2(sc[2 * j + 1][2], sc[2 * j + 1][3]);
#pragma unroll
                for (int p = 0; p < 8; p++) {
                    uint32_t vb[4];
                    ldsm4t(vb, svb + (uint32_t)(voff[p] + j * 16 * QSH) * 4u);
                    mma_f16(acc[2 * p],     pa0, pa1, pa2, pa3, vb[0], vb[1]);
                    mma_f16(acc[2 * p + 1], pa0, pa1, pa2, pa3, vb[2], vb[3]);
                }
            }
        }
    }

    // ---- epilogue: normalize, emit fp16 pair-words ----
    const float inv0 = 1.0f / l0;
    const float inv1 = 1.0f / l1;
    uint32_t* o0 = Oh + (size_t)(b * S_LEN + r0) * (D_MODEL / 2) + h * 64;
    uint32_t* o1 = o0 + (size_t)8 * (D_MODEL / 2);
#pragma unroll
    for (int nf = 0; nf < 16; nf++) {
        const int wc = nf * 4 + q;
        o0[wc] = packh2(acc[nf][0] * inv0, acc[nf][1] * inv0);
        o1[wc] = packh2(acc[nf][2] * inv1, acc[nf][3] * inv1);
    }
}

// ---------------------------------------------------------------------------
// Launch
// ---------------------------------------------------------------------------
extern "C" void kernel_launch(void* const* d_in, const int* in_sizes, int n_in,
                              void* d_out, int out_size)
{
    const float* x     = (const float*)d_in[0];
    const int*   pos32 = (const int*)d_in[1];
    const float* w_qkv = (const float*)d_in[2];
    const float* w_o   = (const float*)d_in[3];
    float* out         = (float*)d_out;

    uint32_t *xh, *wqkvh, *woh, *qh, *kh, *vn, *attnh;
    float2* ctab;
    cudaGetSymbolAddress((void**)&xh,    g_xh);
    cudaGetSymbolAddress((void**)&wqkvh, g_wqkvh);
    cudaGetSymbolAddress((void**)&woh,   g_woh);
    cudaGetSymbolAddress((void**)&qh,    g_qh);
    cudaGetSymbolAddress((void**)&kh,    g_kh);
    cudaGetSymbolAddress((void**)&vn,    g_vn);
    cudaGetSymbolAddress((void**)&attnh, g_attnh);
    cudaGetSymbolAddress((void**)&ctab,  g_ctab);

    cudaFuncSetAttribute(h16_gemm<1>,
                         cudaFuncAttributeMaxDynamicSharedMemorySize, GEMM_SMEM);
    cudaFuncSetAttribute(h16_gemm<0>,
                         cudaFuncAttributeMaxDynamicSharedMemorySize, GEMM_SMEM);
    cudaFuncSetAttribute(flash_h16,
                         cudaFuncAttributeMaxDynamicSharedMemorySize, FLASH_H_SMEM);

    // 0) prep: x -> fp16; weights -> transposed-packed fp16; rope table
    {
        const int nx4 = NTOK * D_MODEL / 4;
        f32_to_h16<<<nx4 / 256, 256>>>((const float4*)x, xh, nx4);
        pack_w16t<<<dim3(QKV_N / 32, D_MODEL / 64), 256>>>(w_qkv, wqkvh,
                                                           QKV_N, D_MODEL);
        pack_w16t<<<dim3(D_MODEL / 32, D_MODEL / 64), 256>>>(w_o, woh,
                                                             D_MODEL, D_MODEL);
        build_ctab<<<S_LEN, 64>>>(ctab, pos32);
    }

    // 1) QKV projection (fp16 HMMA + ldmatrix) with fused RoPE epilogue
    h16_gemm<1><<<dim3(QKV_N / TBN, NTOK / TBM), 128, GEMM_SMEM>>>(
        xh, wqkvh, nullptr, qh, kh, vn, ctab, QKV_N, D_MODEL);

    // 2) causal flash attention (fp16 HMMA + ldmatrix, V via .trans, 2 CTA/SM)
    flash_h16<<<dim3(S_LEN / FQ, NHEADS, BATCH), 256, FLASH_H_SMEM>>>(
        qh, kh, vn, attnh);

    // 3) output projection (fp16 HMMA + ldmatrix) -> f32 out
    h16_gemm<0><<<dim3(D_MODEL / TBN, NTOK / TBM), 128, GEMM_SMEM>>>(
        attnh, woh, out, nullptr, nullptr, nullptr, nullptr, D_MODEL, D_MODEL);
}